// round 4
// baseline (speedup 1.0000x reference)
#include <cuda_runtime.h>
#include <math.h>
#include <stdint.h>

// Problem constants
#define NB 32
#define NS 2048
#define ND 1024

// Scratch (device globals — no allocation allowed)
__device__ float g_dec_proj[NB * ND];                 // 128 KB
__device__ float g_partials[(size_t)NB * NS * 8];     // 2 MB: per-(m, n-tile) partial scores

// ---------------------------------------------------------------------------
// Accurate tanh (immune to --use_fast_math's tanh.approx, whose ~1e-3 rel
// error would blow the error budget after the 1024-wide v-weighted sum).
// ---------------------------------------------------------------------------
__device__ __forceinline__ float tanh_acc(float x) {
    float ax = fabsf(x);
    float e  = __expf(-2.0f * ax);
    float t  = (1.0f - e) / (1.0f + e);
    return copysignf(t, x);
}

// ---------------------------------------------------------------------------
// Kernel 1: dec_proj[b, e] = sum_k dec[b, k] * W_a[e, k]   (Wd = W_a[:, :D])
// grid (32, 8), 256 threads. One warp per output element (coalesced W reads).
// ---------------------------------------------------------------------------
__global__ void k_dec_proj(const float* __restrict__ dec,
                           const float* __restrict__ Wa) {
    __shared__ float ds[ND];
    const int b = blockIdx.x;
    for (int k = threadIdx.x; k < ND; k += blockDim.x)
        ds[k] = dec[b * ND + k];
    __syncthreads();

    const int warp = threadIdx.x >> 5;
    const int lane = threadIdx.x & 31;
    for (int el = warp; el < 128; el += 8) {
        const int e = blockIdx.y * 128 + el;
        const float* w = Wa + (size_t)e * (2 * ND);  // Wd row e (cols [0, D))
        float s = 0.0f;
        for (int k = lane; k < ND; k += 32)
            s = fmaf(ds[k], w[k], s);
        #pragma unroll
        for (int o = 16; o; o >>= 1)
            s += __shfl_xor_sync(0xffffffffu, s, o);
        if (lane == 0)
            g_dec_proj[b * ND + e] = s;
    }
}

// ---------------------------------------------------------------------------
// Kernel 2: fused main GEMM + tanh + v-dot partial reduction.
//   C[m, e] = sum_k enc[m, k] * We[e, k],   We[e,k] = W_a[e*2048 + 1024 + k]
//   partials[m, nblk] = sum_{e in tile} tanh(C[m,e] + dec_proj[b,e]) * v[e]
// Tiles: 128(M) x 128(N) x 16(K), 256 threads, 8x8 microtile, double buffer.
// grid (512, 8). Each M-tile lies inside one batch b (2048 % 128 == 0).
// ---------------------------------------------------------------------------
__global__ __launch_bounds__(256, 2)
void k_gemm_fused(const float* __restrict__ enc,
                  const float* __restrict__ Wa,
                  const float* __restrict__ v) {
    __shared__ float As[2][16][132];   // [buf][k][m], padded
    __shared__ float Bs[2][16][132];   // [buf][k][e], padded

    const int tid = threadIdx.x;
    const int tx  = tid & 15;          // n-thread
    const int ty  = tid >> 4;          // m-thread
    const int m0  = blockIdx.x * 128;
    const int n0  = blockIdx.y * 128;

    // Global-load mapping: 512 float4 per tile per matrix; thread handles
    // rows lrow and lrow+64 at float4-column lk4.
    const int lrow = tid >> 2;          // 0..63
    const int lk4  = (tid & 3) * 4;     // 0,4,8,12

    const float* aP0 = enc + (size_t)(m0 + lrow) * ND + lk4;
    const float* aP1 = aP0 + (size_t)64 * ND;
    const float* bP0 = Wa + (size_t)(n0 + lrow) * (2 * ND) + ND + lk4;  // We
    const float* bP1 = bP0 + (size_t)64 * (2 * ND);

    float acc[8][8];
    #pragma unroll
    for (int i = 0; i < 8; i++)
        #pragma unroll
        for (int j = 0; j < 8; j++)
            acc[i][j] = 0.0f;

    // Prologue: tile 0 -> smem[0]
    {
        float4 a0 = *(const float4*)aP0;
        float4 a1 = *(const float4*)aP1;
        float4 b0 = *(const float4*)bP0;
        float4 b1 = *(const float4*)bP1;
        As[0][lk4 + 0][lrow] = a0.x; As[0][lk4 + 1][lrow] = a0.y;
        As[0][lk4 + 2][lrow] = a0.z; As[0][lk4 + 3][lrow] = a0.w;
        As[0][lk4 + 0][lrow + 64] = a1.x; As[0][lk4 + 1][lrow + 64] = a1.y;
        As[0][lk4 + 2][lrow + 64] = a1.z; As[0][lk4 + 3][lrow + 64] = a1.w;
        Bs[0][lk4 + 0][lrow] = b0.x; Bs[0][lk4 + 1][lrow] = b0.y;
        Bs[0][lk4 + 2][lrow] = b0.z; Bs[0][lk4 + 3][lrow] = b0.w;
        Bs[0][lk4 + 0][lrow + 64] = b1.x; Bs[0][lk4 + 1][lrow + 64] = b1.y;
        Bs[0][lk4 + 2][lrow + 64] = b1.z; Bs[0][lk4 + 3][lrow + 64] = b1.w;
    }
    __syncthreads();

    const int NK = ND / 16;   // 64
    int buf = 0;
    float4 pa0, pa1, pb0, pb1;

    for (int kt = 0; kt < NK; kt++) {
        if (kt + 1 < NK) {
            const int ko = (kt + 1) * 16;
            pa0 = *(const float4*)(aP0 + ko);
            pa1 = *(const float4*)(aP1 + ko);
            pb0 = *(const float4*)(bP0 + ko);
            pb1 = *(const float4*)(bP1 + ko);
        }

        #pragma unroll
        for (int kk = 0; kk < 16; kk++) {
            float4 af0 = *(const float4*)&As[buf][kk][ty * 8];
            float4 af1 = *(const float4*)&As[buf][kk][ty * 8 + 4];
            float4 bf0 = *(const float4*)&Bs[buf][kk][tx * 8];
            float4 bf1 = *(const float4*)&Bs[buf][kk][tx * 8 + 4];
            float a[8] = {af0.x, af0.y, af0.z, af0.w, af1.x, af1.y, af1.z, af1.w};
            float bb[8] = {bf0.x, bf0.y, bf0.z, bf0.w, bf1.x, bf1.y, bf1.z, bf1.w};
            #pragma unroll
            for (int i = 0; i < 8; i++)
                #pragma unroll
                for (int j = 0; j < 8; j++)
                    acc[i][j] = fmaf(a[i], bb[j], acc[i][j]);
        }

        if (kt + 1 < NK) {
            // Safe: smem[buf^1]'s readers passed the sync that ended iter kt-1.
            const int nb = buf ^ 1;
            As[nb][lk4 + 0][lrow] = pa0.x; As[nb][lk4 + 1][lrow] = pa0.y;
            As[nb][lk4 + 2][lrow] = pa0.z; As[nb][lk4 + 3][lrow] = pa0.w;
            As[nb][lk4 + 0][lrow + 64] = pa1.x; As[nb][lk4 + 1][lrow + 64] = pa1.y;
            As[nb][lk4 + 2][lrow + 64] = pa1.z; As[nb][lk4 + 3][lrow + 64] = pa1.w;
            Bs[nb][lk4 + 0][lrow] = pb0.x; Bs[nb][lk4 + 1][lrow] = pb0.y;
            Bs[nb][lk4 + 2][lrow] = pb0.z; Bs[nb][lk4 + 3][lrow] = pb0.w;
            Bs[nb][lk4 + 0][lrow + 64] = pb1.x; Bs[nb][lk4 + 1][lrow + 64] = pb1.y;
            Bs[nb][lk4 + 2][lrow + 64] = pb1.z; Bs[nb][lk4 + 3][lrow + 64] = pb1.w;
            __syncthreads();
            buf = nb;
        }
    }

    // Epilogue: tanh(acc + dec_proj) * v, reduce over the 128 e-columns.
    const int b = m0 >> 11;   // m0 / 2048
    float dvec[8], vv[8];
    #pragma unroll
    for (int j = 0; j < 8; j++) {
        const int e = n0 + tx * 8 + j;
        dvec[j] = g_dec_proj[b * ND + e];
        vv[j]   = v[e];
    }
    float rsum[8];
    #pragma unroll
    for (int i = 0; i < 8; i++) {
        float s = 0.0f;
        #pragma unroll
        for (int j = 0; j < 8; j++)
            s = fmaf(tanh_acc(acc[i][j] + dvec[j]), vv[j], s);
        rsum[i] = s;
    }

    __syncthreads();                 // all mainloop smem reads done
    float* red = &As[0][0][0];       // reuse: need 128*16 = 2048 floats
    #pragma unroll
    for (int i = 0; i < 8; i++)
        red[(ty * 8 + i) * 16 + tx] = rsum[i];
    __syncthreads();

    if (tid < 128) {
        float s = 0.0f;
        #pragma unroll
        for (int t = 0; t < 16; t++)
            s += red[tid * 16 + t];
        g_partials[((size_t)(m0 + tid)) * 8 + blockIdx.y] = s;
    }
}

// ---------------------------------------------------------------------------
// Kernel 3: per-batch softmax over s (sums the 8 n-tile partials first).
// grid 32, 256 threads.
// ---------------------------------------------------------------------------
__global__ void k_softmax(float* __restrict__ out) {
    __shared__ float sc[NS];
    __shared__ float wred[8];
    const int b   = blockIdx.x;
    const int tid = threadIdx.x;
    const int warp = tid >> 5, lane = tid & 31;

    float mx = -1e30f;
    for (int s = tid; s < NS; s += 256) {
        const float* p = &g_partials[((size_t)(b * NS + s)) * 8];
        float t = ((p[0] + p[1]) + (p[2] + p[3])) + ((p[4] + p[5]) + (p[6] + p[7]));
        sc[s] = t;
        mx = fmaxf(mx, t);
    }
    #pragma unroll
    for (int o = 16; o; o >>= 1)
        mx = fmaxf(mx, __shfl_xor_sync(0xffffffffu, mx, o));
    if (lane == 0) wred[warp] = mx;
    __syncthreads();
    if (tid == 0) {
        float m = wred[0];
        #pragma unroll
        for (int i = 1; i < 8; i++) m = fmaxf(m, wred[i]);
        wred[0] = m;
    }
    __syncthreads();
    const float bm = wred[0];
    __syncthreads();   // wred[0] consumed before reuse below

    float sum = 0.0f;
    for (int s = tid; s < NS; s += 256) {
        float e = __expf(sc[s] - bm);
        sc[s] = e;
        sum += e;
    }
    #pragma unroll
    for (int o = 16; o; o >>= 1)
        sum += __shfl_xor_sync(0xffffffffu, sum, o);
    if (lane == 0) wred[warp] = sum;
    __syncthreads();
    if (tid == 0) {
        float t = 0.0f;
        #pragma unroll
        for (int i = 0; i < 8; i++) t += wred[i];
        wred[0] = t;
    }
    __syncthreads();
    const float inv = 1.0f / wred[0];
    for (int s = tid; s < NS; s += 256)
        out[b * NS + s] = sc[s] * inv;
}

// ---------------------------------------------------------------------------
// Launch
// Inputs: [0] decoder_hidden (32*1024), [1] encoder_all_hidden (32*2048*1024),
//         [2] W_a (1024*2048), [3] v (1024). Output: alpha (32*2048) fp32.
// ---------------------------------------------------------------------------
extern "C" void kernel_launch(void* const* d_in, const int* in_sizes, int n_in,
                              void* d_out, int out_size) {
    const float* dec = (const float*)d_in[0];
    const float* enc = (const float*)d_in[1];
    const float* Wa  = (const float*)d_in[2];
    const float* v   = (const float*)d_in[3];
    float* out = (float*)d_out;
    (void)in_sizes; (void)n_in; (void)out_size;

    k_dec_proj<<<dim3(NB, 8), 256>>>(dec, Wa);
    k_gemm_fused<<<dim3(512, 8), 256>>>(enc, Wa, v);
    k_softmax<<<NB, 256>>>(out);
}

// round 5
// speedup vs baseline: 1.0017x; 1.0017x over previous
#include <cuda_runtime.h>
#include <math.h>
#include <stdint.h>

// Problem constants
#define NB 32
#define NS 2048
#define ND 1024

// Scratch (device globals — no allocation allowed)
__device__ float g_dec_proj[NB * ND];                 // 128 KB
__device__ float g_partials[(size_t)NB * NS * 8];     // 2 MB: per-(m, n-tile) partial scores

// ---------------------------------------------------------------------------
// Accurate tanh (immune to --use_fast_math's tanh.approx, whose ~1e-3 rel
// error would blow the error budget after the 1024-wide v-weighted sum).
// ---------------------------------------------------------------------------
__device__ __forceinline__ float tanh_acc(float x) {
    float ax = fabsf(x);
    float e  = __expf(-2.0f * ax);
    float t  = (1.0f - e) / (1.0f + e);
    return copysignf(t, x);
}

// ---------------------------------------------------------------------------
// Kernel 1: dec_proj[b, e] = sum_k dec[b, k] * W_a[e, k]   (Wd = W_a[:, :D])
// grid (32, 8), 256 threads. One warp per output element (coalesced W reads).
// ---------------------------------------------------------------------------
__global__ void k_dec_proj(const float* __restrict__ dec,
                           const float* __restrict__ Wa) {
    __shared__ float ds[ND];
    const int b = blockIdx.x;
    for (int k = threadIdx.x; k < ND; k += blockDim.x)
        ds[k] = dec[b * ND + k];
    __syncthreads();

    const int warp = threadIdx.x >> 5;
    const int lane = threadIdx.x & 31;
    for (int el = warp; el < 128; el += 8) {
        const int e = blockIdx.y * 128 + el;
        const float* w = Wa + (size_t)e * (2 * ND);  // Wd row e (cols [0, D))
        float s = 0.0f;
        for (int k = lane; k < ND; k += 32)
            s = fmaf(ds[k], w[k], s);
        #pragma unroll
        for (int o = 16; o; o >>= 1)
            s += __shfl_xor_sync(0xffffffffu, s, o);
        if (lane == 0)
            g_dec_proj[b * ND + e] = s;
    }
}

// ---------------------------------------------------------------------------
// Kernel 2: fused main GEMM + tanh + v-dot partial reduction.
//   C[m, e] = sum_k enc[m, k] * We[e, k],   We[e,k] = W_a[e*2048 + 1024 + k]
//   partials[m, nblk] = sum_{e in tile} tanh(C[m,e] + dec_proj[b,e]) * v[e]
// Tiles: 128(M) x 128(N) x 16(K), 256 threads, 8x8 microtile, double buffer.
// grid (512, 8). Each M-tile lies inside one batch b (2048 % 128 == 0).
// ---------------------------------------------------------------------------
__global__ __launch_bounds__(256, 2)
void k_gemm_fused(const float* __restrict__ enc,
                  const float* __restrict__ Wa,
                  const float* __restrict__ v) {
    __shared__ float As[2][16][132];   // [buf][k][m], padded
    __shared__ float Bs[2][16][132];   // [buf][k][e], padded

    const int tid = threadIdx.x;
    const int tx  = tid & 15;          // n-thread
    const int ty  = tid >> 4;          // m-thread
    const int m0  = blockIdx.x * 128;
    const int n0  = blockIdx.y * 128;

    // Global-load mapping: 512 float4 per tile per matrix; thread handles
    // rows lrow and lrow+64 at float4-column lk4.
    const int lrow = tid >> 2;          // 0..63
    const int lk4  = (tid & 3) * 4;     // 0,4,8,12

    const float* aP0 = enc + (size_t)(m0 + lrow) * ND + lk4;
    const float* aP1 = aP0 + (size_t)64 * ND;
    const float* bP0 = Wa + (size_t)(n0 + lrow) * (2 * ND) + ND + lk4;  // We
    const float* bP1 = bP0 + (size_t)64 * (2 * ND);

    float acc[8][8];
    #pragma unroll
    for (int i = 0; i < 8; i++)
        #pragma unroll
        for (int j = 0; j < 8; j++)
            acc[i][j] = 0.0f;

    // Prologue: tile 0 -> smem[0]
    {
        float4 a0 = *(const float4*)aP0;
        float4 a1 = *(const float4*)aP1;
        float4 b0 = *(const float4*)bP0;
        float4 b1 = *(const float4*)bP1;
        As[0][lk4 + 0][lrow] = a0.x; As[0][lk4 + 1][lrow] = a0.y;
        As[0][lk4 + 2][lrow] = a0.z; As[0][lk4 + 3][lrow] = a0.w;
        As[0][lk4 + 0][lrow + 64] = a1.x; As[0][lk4 + 1][lrow + 64] = a1.y;
        As[0][lk4 + 2][lrow + 64] = a1.z; As[0][lk4 + 3][lrow + 64] = a1.w;
        Bs[0][lk4 + 0][lrow] = b0.x; Bs[0][lk4 + 1][lrow] = b0.y;
        Bs[0][lk4 + 2][lrow] = b0.z; Bs[0][lk4 + 3][lrow] = b0.w;
        Bs[0][lk4 + 0][lrow + 64] = b1.x; Bs[0][lk4 + 1][lrow + 64] = b1.y;
        Bs[0][lk4 + 2][lrow + 64] = b1.z; Bs[0][lk4 + 3][lrow + 64] = b1.w;
    }
    __syncthreads();

    const int NK = ND / 16;   // 64
    int buf = 0;
    float4 pa0, pa1, pb0, pb1;

    for (int kt = 0; kt < NK; kt++) {
        if (kt + 1 < NK) {
            const int ko = (kt + 1) * 16;
            pa0 = *(const float4*)(aP0 + ko);
            pa1 = *(const float4*)(aP1 + ko);
            pb0 = *(const float4*)(bP0 + ko);
            pb1 = *(const float4*)(bP1 + ko);
        }

        #pragma unroll
        for (int kk = 0; kk < 16; kk++) {
            float4 af0 = *(const float4*)&As[buf][kk][ty * 8];
            float4 af1 = *(const float4*)&As[buf][kk][ty * 8 + 4];
            float4 bf0 = *(const float4*)&Bs[buf][kk][tx * 8];
            float4 bf1 = *(const float4*)&Bs[buf][kk][tx * 8 + 4];
            float a[8] = {af0.x, af0.y, af0.z, af0.w, af1.x, af1.y, af1.z, af1.w};
            float bb[8] = {bf0.x, bf0.y, bf0.z, bf0.w, bf1.x, bf1.y, bf1.z, bf1.w};
            #pragma unroll
            for (int i = 0; i < 8; i++)
                #pragma unroll
                for (int j = 0; j < 8; j++)
                    acc[i][j] = fmaf(a[i], bb[j], acc[i][j]);
        }

        if (kt + 1 < NK) {
            // Safe: smem[buf^1]'s readers passed the sync that ended iter kt-1.
            const int nb = buf ^ 1;
            As[nb][lk4 + 0][lrow] = pa0.x; As[nb][lk4 + 1][lrow] = pa0.y;
            As[nb][lk4 + 2][lrow] = pa0.z; As[nb][lk4 + 3][lrow] = pa0.w;
            As[nb][lk4 + 0][lrow + 64] = pa1.x; As[nb][lk4 + 1][lrow + 64] = pa1.y;
            As[nb][lk4 + 2][lrow + 64] = pa1.z; As[nb][lk4 + 3][lrow + 64] = pa1.w;
            Bs[nb][lk4 + 0][lrow] = pb0.x; Bs[nb][lk4 + 1][lrow] = pb0.y;
            Bs[nb][lk4 + 2][lrow] = pb0.z; Bs[nb][lk4 + 3][lrow] = pb0.w;
            Bs[nb][lk4 + 0][lrow + 64] = pb1.x; Bs[nb][lk4 + 1][lrow + 64] = pb1.y;
            Bs[nb][lk4 + 2][lrow + 64] = pb1.z; Bs[nb][lk4 + 3][lrow + 64] = pb1.w;
            __syncthreads();
            buf = nb;
        }
    }

    // Epilogue: tanh(acc + dec_proj) * v, reduce over the 128 e-columns.
    const int b = m0 >> 11;   // m0 / 2048
    float dvec[8], vv[8];
    #pragma unroll
    for (int j = 0; j < 8; j++) {
        const int e = n0 + tx * 8 + j;
        dvec[j] = g_dec_proj[b * ND + e];
        vv[j]   = v[e];
    }
    float rsum[8];
    #pragma unroll
    for (int i = 0; i < 8; i++) {
        float s = 0.0f;
        #pragma unroll
        for (int j = 0; j < 8; j++)
            s = fmaf(tanh_acc(acc[i][j] + dvec[j]), vv[j], s);
        rsum[i] = s;
    }

    __syncthreads();                 // all mainloop smem reads done
    float* red = &As[0][0][0];       // reuse: need 128*16 = 2048 floats
    #pragma unroll
    for (int i = 0; i < 8; i++)
        red[(ty * 8 + i) * 16 + tx] = rsum[i];
    __syncthreads();

    if (tid < 128) {
        float s = 0.0f;
        #pragma unroll
        for (int t = 0; t < 16; t++)
            s += red[tid * 16 + t];
        g_partials[((size_t)(m0 + tid)) * 8 + blockIdx.y] = s;
    }
}

// ---------------------------------------------------------------------------
// Kernel 3: per-batch softmax over s (sums the 8 n-tile partials first).
// grid 32, 256 threads.
// ---------------------------------------------------------------------------
__global__ void k_softmax(float* __restrict__ out) {
    __shared__ float sc[NS];
    __shared__ float wred[8];
    const int b   = blockIdx.x;
    const int tid = threadIdx.x;
    const int warp = tid >> 5, lane = tid & 31;

    float mx = -1e30f;
    for (int s = tid; s < NS; s += 256) {
        const float* p = &g_partials[((size_t)(b * NS + s)) * 8];
        float t = ((p[0] + p[1]) + (p[2] + p[3])) + ((p[4] + p[5]) + (p[6] + p[7]));
        sc[s] = t;
        mx = fmaxf(mx, t);
    }
    #pragma unroll
    for (int o = 16; o; o >>= 1)
        mx = fmaxf(mx, __shfl_xor_sync(0xffffffffu, mx, o));
    if (lane == 0) wred[warp] = mx;
    __syncthreads();
    if (tid == 0) {
        float m = wred[0];
        #pragma unroll
        for (int i = 1; i < 8; i++) m = fmaxf(m, wred[i]);
        wred[0] = m;
    }
    __syncthreads();
    const float bm = wred[0];
    __syncthreads();   // wred[0] consumed before reuse below

    float sum = 0.0f;
    for (int s = tid; s < NS; s += 256) {
        float e = __expf(sc[s] - bm);
        sc[s] = e;
        sum += e;
    }
    #pragma unroll
    for (int o = 16; o; o >>= 1)
        sum += __shfl_xor_sync(0xffffffffu, sum, o);
    if (lane == 0) wred[warp] = sum;
    __syncthreads();
    if (tid == 0) {
        float t = 0.0f;
        #pragma unroll
        for (int i = 0; i < 8; i++) t += wred[i];
        wred[0] = t;
    }
    __syncthreads();
    const float inv = 1.0f / wred[0];
    for (int s = tid; s < NS; s += 256)
        out[b * NS + s] = sc[s] * inv;
}

// ---------------------------------------------------------------------------
// Launch
// Inputs: [0] decoder_hidden (32*1024), [1] encoder_all_hidden (32*2048*1024),
//         [2] W_a (1024*2048), [3] v (1024). Output: alpha (32*2048) fp32.
// ---------------------------------------------------------------------------
extern "C" void kernel_launch(void* const* d_in, const int* in_sizes, int n_in,
                              void* d_out, int out_size) {
    const float* dec = (const float*)d_in[0];
    const float* enc = (const float*)d_in[1];
    const float* Wa  = (const float*)d_in[2];
    const float* v   = (const float*)d_in[3];
    float* out = (float*)d_out;
    (void)in_sizes; (void)n_in; (void)out_size;

    k_dec_proj<<<dim3(NB, 8), 256>>>(dec, Wa);
    k_gemm_fused<<<dim3(512, 8), 256>>>(enc, Wa, v);
    k_softmax<<<NB, 256>>>(out);
}